// round 15
// baseline (speedup 1.0000x reference)
#include <cuda_runtime.h>

// ---------------- constants ----------------
#define D0 65
#define DD 4225          // 65*65
#define DDD 274625       // 65*65*65
#define S 32
#define SSS 32768        // 32^3
#define NB 2
#define C2 32
#define CO 100
#define G 16             // sites per block in invconv
#define GP 20            // padded site stride in h2s (mult of 4 for 8B alignment)
#define LIST_STRIDE 8192
// padded h1 dims (1-voxel zero halo)
#define PROW 34          // x stride = 1, y stride = 34
#define PSLAB 1156       // 34*34
#define PVOL 39304       // 34*34*34
// fused grids
#define CONV1_BLOCKS 256
#define BL_BLOCKS 2146       // ceil(NB*DDD/256)
#define CONV2_BLOCKS 512

// ---------------- static scratch ----------------
__device__ float g_h1[NB*C2*PVOL];  // PLANAR PADDED [n][c][z+1][y+1][x+1]; halo stays 0
__device__ float g_h2[NB*SSS*C2];   // channels-last [n][z][y][x][c]
__device__ float g_m1[NB*SSS];
__device__ float g_W2T[27*32*32];   // [tap][ci][co]
__device__ float g_WT[27*32*100];   // [tap][ci][co]
__device__ float g_a2[32], g_k2[32];
__device__ int   g_list[8*LIST_STRIDE];
__device__ int   g_cnt[8];

// ---------------- f32x2 helpers ----------------
__device__ __forceinline__ void ffma2(unsigned long long &d, unsigned long long a, unsigned long long b) {
    asm("fma.rn.f32x2 %0, %1, %2, %0;" : "+l"(d) : "l"(a), "l"(b));
}
__device__ __forceinline__ unsigned long long pack2(float x) {
    unsigned long long r;
    asm("mov.b64 %0, {%1, %1};" : "=l"(r) : "f"(x));
    return r;
}
__device__ __forceinline__ float2 unpack2(unsigned long long v) {
    float2 r;
    asm("mov.b64 {%0, %1}, %2;" : "=f"(r.x), "=f"(r.y) : "l"(v));
    return r;
}

// ---------------- prep: fold BN2, transpose weights, reset counters ----------------
__global__ void prep_kernel(const float* __restrict__ W2, const float* __restrict__ Winv,
                            const float* __restrict__ b2, const float* __restrict__ g2,
                            const float* __restrict__ bt2, const float* __restrict__ rm2,
                            const float* __restrict__ rv2) {
    int tid = blockIdx.x * blockDim.x + threadIdx.x;
    int nth = gridDim.x * blockDim.x;
    if (tid < 8) g_cnt[tid] = 0;
    if (tid < 32) {
        float a2 = g2[tid] * rsqrtf(rv2[tid] + 1e-5f);
        g_a2[tid] = a2;
        g_k2[tid] = (b2[tid] - rm2[tid]) * a2 + bt2[tid];
    }
    for (int i = tid; i < 27 * 32 * 32; i += nth) {
        int k = i / 1024, r = i % 1024, ci = r / 32, co = r % 32;
        g_W2T[i] = W2[(co * 32 + ci) * 27 + k];
    }
    for (int i = tid; i < 27 * 32 * 100; i += nth) {
        int k = i / 3200, r = i % 3200, ci = r / 100, co = r % 100;
        g_WT[i] = Winv[(co * 32 + ci) * 27 + k];
    }
}

// ---------------- FUSED conv1 + buildlist (both depend only on prep) --------------
__global__ __launch_bounds__(256) void conv1_aux_kernel(
        const float* __restrict__ x, const int* __restrict__ mask0,
        const float* __restrict__ W1,
        const float* __restrict__ b1, const float* __restrict__ g1,
        const float* __restrict__ bt1, const float* __restrict__ rm1,
        const float* __restrict__ rv1) {
    int b = blockIdx.x;
    int tid = threadIdx.x;

    if (b >= CONV1_BLOCKS) {
        // ---- buildlist branch ----
        __shared__ int lc[8], lb[8];
        int i = (b - CONV1_BLOCKS) * 256 + tid;
        if (tid < 8) lc[tid] = 0;
        __syncthreads();
        int cls = -1, myp = 0;
        if (i < NB * DDD && mask0[i]) {
            int r = i % DDD;
            int oz = r / DD;
            int r2 = r % DD;
            int oy = r2 / D0;
            int ox = r2 % D0;
            cls = ((oz & 1) << 2) | ((oy & 1) << 1) | (ox & 1);
            myp = atomicAdd(&lc[cls], 1);
        }
        __syncthreads();
        if (tid < 8 && lc[tid] > 0) lb[tid] = atomicAdd(&g_cnt[tid], lc[tid]);
        __syncthreads();
        if (cls >= 0) g_list[cls * LIST_STRIDE + lb[cls] + myp] = i;
        return;
    }

    // ---- conv1 branch: 256 thr = 32x * 8oy ----
    __shared__ float w1s[27 * 32];
    __shared__ float a1s[32], k1s[32];
    for (int i = tid; i < 864; i += 256) {
        int k = i >> 5, c = i & 31;
        w1s[i] = W1[c * 27 + k];
    }
    if (tid < 32) {
        float a = g1[tid] * rsqrtf(rv1[tid] + 1e-5f);
        a1s[tid] = a;
        k1s[tid] = (b1[tid] - rm1[tid]) * a + bt1[tid];
    }
    __syncthreads();

    int bx = b & 3;
    int oz = (b >> 2) & 31;
    int n  = b >> 7;
    int ox = tid & 31;
    int oy = bx * 8 + (tid >> 5);

    float acc[32];
#pragma unroll
    for (int c = 0; c < 32; c++) acc[c] = 0.f;
    int cnt = 0;
    const float* xb = x + n * DDD;
    const int*   mb = mask0 + n * DDD;

    for (int kd = 0; kd < 3; kd++)
        for (int kh = 0; kh < 3; kh++) {
            int base = (2 * oz + kd) * DD + (2 * oy + kh) * D0 + 2 * ox;
#pragma unroll
            for (int kw = 0; kw < 3; kw++) {
                float v = xb[base + kw];
                cnt += mb[base + kw];
                const float* wq = &w1s[((kd * 3 + kh) * 3 + kw) * 32];
#pragma unroll
                for (int c = 0; c < 32; c++) acc[c] += v * wq[c];
            }
        }

    float m = (cnt > 0) ? 1.f : 0.f;
    g_m1[n * SSS + (oz * S + oy) * S + ox] = m;
    float* hp = &g_h1[n * (C2 * PVOL) + (oz + 1) * PSLAB + (oy + 1) * PROW + (ox + 1)];
#pragma unroll
    for (int c = 0; c < 32; c++)
        hp[c * PVOL] = fmaxf(acc[c] * a1s[c] + k1s[c], 0.f) * m;
}

// ---------------- FUSED conv2 + zero-fill ----------------------------------------
__global__ __launch_bounds__(256) void conv2_zero_kernel(float* __restrict__ out, int out_size) {
    int b = blockIdx.x;
    int tid = threadIdx.x;

    if (b >= CONV2_BLOCKS) {
        // ---- zero branch ----
        int zb = b - CONV2_BLOCKS;
        int n4 = out_size >> 2;
        float4* o4 = (float4*)out;
        float4 z = make_float4(0.f, 0.f, 0.f, 0.f);
        int base = zb * 1024 + tid;
#pragma unroll
        for (int k = 0; k < 4; k++) {
            int idx = base + k * 256;
            if (idx < n4) o4[idx] = z;
        }
        if (zb == 0 && tid == 0)
            for (int j = n4 << 2; j < out_size; j++) out[j] = 0.f;
        return;
    }

    // ---- conv2 branch ----
    extern __shared__ float w2s[];   // [tap][ci][co 16 for this half]
    int ch = b & 1;
    {
        const float4* src = (const float4*)g_W2T;
        float4* dst = (float4*)w2s;
        for (int i = tid; i < 27 * 32 * 4; i += 256) {
            int tc = i >> 2, j = i & 3;
            dst[tc * 4 + j] = src[tc * 8 + ch * 4 + j];
        }
    }
    __syncthreads();

    int xh = tid & 15;
    int cq = (tid >> 4) & 1;
    int oy = ((b >> 1) & 3) * 8 + (tid >> 5);
    int oz = (b >> 3) & 31;
    int n  = b >> 8;
    int cob = cq * 8;
    int cobase = ch * 16 + cob;

    unsigned long long accA[4], accB[4];
#pragma unroll
    for (int i = 0; i < 4; i++) { accA[i] = 0ull; accB[i] = 0ull; }

    const float* hbase = g_h1 + n * (C2 * PVOL) + oz * PSLAB + oy * PROW + 2 * xh;

#pragma unroll
    for (int kd = 0; kd < 3; kd++) {
#pragma unroll
        for (int kh = 0; kh < 3; kh++) {
            const float* rowp = hbase + kd * PSLAB + kh * PROW;
            int tap0 = (kd * 3 + kh) * 3;
            const float* wt0 = &w2s[(tap0 + 0) * 512 + cob];
            const float* wt1 = &w2s[(tap0 + 1) * 512 + cob];
            const float* wt2 = &w2s[(tap0 + 2) * 512 + cob];
#pragma unroll 4
            for (int ci = 0; ci < 32; ci++) {
                const float2* rp2 = (const float2*)(rowp + ci * PVOL);
                float2 p01 = rp2[0];
                float2 p23 = rp2[1];
                unsigned long long hh0 = pack2(p01.x);
                unsigned long long hh1 = pack2(p01.y);
                unsigned long long hh2 = pack2(p23.x);
                unsigned long long hh3 = pack2(p23.y);
                const ulonglong2* wq0 = (const ulonglong2*)(wt0 + ci * 16);
                const ulonglong2* wq1 = (const ulonglong2*)(wt1 + ci * 16);
                const ulonglong2* wq2 = (const ulonglong2*)(wt2 + ci * 16);
#pragma unroll
                for (int q = 0; q < 2; q++) {
                    ulonglong2 w0 = wq0[q];
                    ulonglong2 w1 = wq1[q];
                    ulonglong2 w2 = wq2[q];
                    ffma2(accA[2 * q],     w0.x, hh0);
                    ffma2(accA[2 * q + 1], w0.y, hh0);
                    ffma2(accB[2 * q],     w0.x, hh1);
                    ffma2(accB[2 * q + 1], w0.y, hh1);
                    ffma2(accA[2 * q],     w1.x, hh1);
                    ffma2(accA[2 * q + 1], w1.y, hh1);
                    ffma2(accB[2 * q],     w1.x, hh2);
                    ffma2(accB[2 * q + 1], w1.y, hh2);
                    ffma2(accA[2 * q],     w2.x, hh2);
                    ffma2(accA[2 * q + 1], w2.y, hh2);
                    ffma2(accB[2 * q],     w2.x, hh3);
                    ffma2(accB[2 * q + 1], w2.y, hh3);
                }
            }
        }
    }

    int loc0 = (oz * S + oy) * S + 2 * xh;
    float m0 = g_m1[n * SSS + loc0];
    float m1v = g_m1[n * SSS + loc0 + 1];
    float* op0 = &g_h2[(n * SSS + loc0) * 32 + cobase];
    float* op1 = op0 + 32;
#pragma unroll
    for (int j = 0; j < 4; j++) {
        float2 va = unpack2(accA[j]);
        float2 vb = unpack2(accB[j]);
        int c0 = cobase + 2 * j, c1 = c0 + 1;
        float a0 = g_a2[c0], a1 = g_a2[c1], k0 = g_k2[c0], k1 = g_k2[c1];
        op0[2 * j]     = fmaxf(va.x * a0 + k0, 0.f) * m0;
        op0[2 * j + 1] = fmaxf(va.y * a1 + k1, 0.f) * m0;
        op1[2 * j]     = fmaxf(vb.x * a0 + k0, 0.f) * m1v;
        op1[2 * j + 1] = fmaxf(vb.y * a1 + k1, 0.f) * m1v;
    }
}

// ---------------- inverse conv: G=16 sites/block (20.5KB smem -> 11 blocks/SM) ------
// grid = (512, 8): blockIdx.y = parity class; 128 threads (co = tid)
__global__ __launch_bounds__(128) void invconv_kernel(const float* __restrict__ binv,
                                                      float* __restrict__ out) {
    int cls = blockIdx.y;
    int count = g_cnt[cls];
    int base = blockIdx.x * G;
    if (base >= count) return;

    int pz = (cls >> 2) & 1, py = (cls >> 1) & 1, px = cls & 1;
    int ndz = pz ? 1 : 2, ndy = py ? 1 : 2, ndx = px ? 1 : 2;
    int numT = ndz * ndy * ndx;

    __shared__ float h2s[8 * 32 * GP];   // [t][ci][pad GP] g fastest
    __shared__ int   sbase[G * 8];
    __shared__ int   kmap[8];
    __shared__ int   ssite[G];
    __shared__ int   sout[G];

    int tid = threadIdx.x;
    int ng = count - base;
    if (ng > G) ng = G;

    if (tid < ng) {
        int s = g_list[cls * LIST_STRIDE + base + tid];
        ssite[tid] = s;
        sout[tid] = s + ((s >= DDD) ? 99 * DDD : 0);   // n*CO*DDD + r (co added later)
    }
    if (tid < numT) {
        int t = tid;
        int tz = t / (ndy * ndx), ty = (t / ndx) % ndy, tx = t % ndx;
        int kd = pz ? 1 : tz * 2, kh = py ? 1 : ty * 2, kw = px ? 1 : tx * 2;
        kmap[t] = (kd * 3 + kh) * 3 + kw;
    }
    __syncthreads();

    for (int i = tid; i < ng * numT; i += 128) {
        int g = i / numT, t = i % numT;
        int s = ssite[g];
        int n = s / DDD;
        int r = s % DDD;
        int oz = r / DD;
        int r2 = r % DD;
        int oy = r2 / D0;
        int ox = r2 % D0;
        int tz = t / (ndy * ndx), ty = (t / ndx) % ndy, tx = t % ndx;
        int kd = pz ? 1 : tz * 2, kh = py ? 1 : ty * 2, kw = px ? 1 : tx * 2;
        int iz = (oz + kd - 2) >> 1;
        int iy = (oy + kh - 2) >> 1;
        int ix = (ox + kw - 2) >> 1;
        bool v = ((unsigned)iz < 32u) && ((unsigned)iy < 32u) && ((unsigned)ix < 32u);
        sbase[g * 8 + t] = v ? ((((n * S + iz) * S + iy) * S + ix) * 32) : -1;
    }
    __syncthreads();

    // cooperative load of h2 tap rows (source ci-coalesced, dest [t][ci][g])
    for (int i = tid; i < G * numT * 32; i += 128) {
        int ci = i & 31;
        int gt = i >> 5;
        int g = gt / numT, t = gt % numT;
        int b = (g < ng) ? sbase[g * 8 + t] : -1;
        h2s[(t * 32 + ci) * GP + g] = (b >= 0) ? g_h2[b + ci] : 0.f;
    }
    __syncthreads();

    int co = tid;
    bool cok = (co < CO);
    float bv = cok ? __ldg(&binv[co]) : 0.f;
    unsigned long long acc2[8];           // G=16 floats = 8 f32x2
    unsigned long long bb = pack2(bv);
#pragma unroll
    for (int j = 0; j < 8; j++) acc2[j] = bb;

    for (int t = 0; t < numT; t++) {
        const float* wp = g_WT + kmap[t] * 3200 + co;
        const float* hb = &h2s[(t * 32) * GP];
#pragma unroll 4
        for (int ci = 0; ci < 32; ci++) {
            float w = cok ? __ldg(wp + ci * 100) : 0.f;
            unsigned long long ww = pack2(w);
            const ulonglong2* hq = (const ulonglong2*)(hb + ci * GP);
#pragma unroll
            for (int q = 0; q < 4; q++) {
                ulonglong2 hv = hq[q];
                ffma2(acc2[2 * q],     ww, hv.x);
                ffma2(acc2[2 * q + 1], ww, hv.y);
            }
        }
    }

    if (cok) {
        int cd = co * DDD;
#pragma unroll
        for (int j = 0; j < 8; j++) {
            float2 v = unpack2(acc2[j]);
            int g0 = 2 * j, g1 = 2 * j + 1;
            if (g0 < ng) out[sout[g0] + cd] = v.x;
            if (g1 < ng) out[sout[g1] + cd] = v.y;
        }
    }
}

// ---------------- launch ----------------
extern "C" void kernel_launch(void* const* d_in, const int* in_sizes, int n_in,
                              void* d_out, int out_size) {
    const float* x    = (const float*)d_in[0];
    const int*   mask0 = (const int*)d_in[1];
    const float* W1   = (const float*)d_in[2];
    const float* b1   = (const float*)d_in[3];
    const float* g1   = (const float*)d_in[4];
    const float* bt1  = (const float*)d_in[5];
    const float* rm1  = (const float*)d_in[6];
    const float* rv1  = (const float*)d_in[7];
    const float* W2   = (const float*)d_in[8];
    const float* b2   = (const float*)d_in[9];
    const float* g2   = (const float*)d_in[10];
    const float* bt2  = (const float*)d_in[11];
    const float* rm2  = (const float*)d_in[12];
    const float* rv2  = (const float*)d_in[13];
    const float* Winv = (const float*)d_in[14];
    const float* binv = (const float*)d_in[15];
    float* out = (float*)d_out;

    cudaFuncSetAttribute(conv2_zero_kernel, cudaFuncAttributeMaxDynamicSharedMemorySize,
                         27 * 32 * 16 * (int)sizeof(float));

    prep_kernel<<<512, 256>>>(W2, Winv, b2, g2, bt2, rm2, rv2);
    conv1_aux_kernel<<<CONV1_BLOCKS + BL_BLOCKS, 256>>>(x, mask0, W1, b1, g1, bt1, rm1, rv1);

    int n4 = out_size >> 2;
    int zblocks = (n4 + 1023) / 1024;
    conv2_zero_kernel<<<CONV2_BLOCKS + zblocks, 256, 27 * 32 * 16 * sizeof(float)>>>(out, out_size);

    invconv_kernel<<<dim3(LIST_STRIDE / G, 8), 128>>>(binv, out);
}

// round 16
// speedup vs baseline: 1.0335x; 1.0335x over previous
#include <cuda_runtime.h>

// ---------------- constants ----------------
#define D0 65
#define DD 4225          // 65*65
#define DDD 274625       // 65*65*65
#define S 32
#define SSS 32768        // 32^3
#define NB 2
#define C2 32
#define CO 100
#define G 32             // sites per block in invconv
#define GP 36            // padded site stride in h2s
#define LIST_STRIDE 8192
// padded h1 dims (1-voxel zero halo)
#define PROW 34          // x stride = 1, y stride = 34
#define PSLAB 1156       // 34*34
#define PVOL 39304       // 34*34*34
// fused grids
#define CONV1_BLOCKS 256
#define BL_BLOCKS 2146       // ceil(NB*DDD/256)
#define CONV2_BLOCKS 512

// ---------------- static scratch ----------------
__device__ float g_h1[NB*C2*PVOL];  // PLANAR PADDED [n][c][z+1][y+1][x+1]; halo stays 0
__device__ float g_h2[NB*SSS*C2];   // channels-last [n][z][y][x][c]
__device__ float g_m1[NB*SSS];
__device__ float g_W2T[27*32*32];   // [tap][ci][co]
__device__ float g_WT[27*32*100];   // [tap][ci][co]
__device__ float g_a2[32], g_k2[32];
__device__ int   g_list[8*LIST_STRIDE];
__device__ int   g_cnt[8];

// ---------------- f32x2 helpers ----------------
__device__ __forceinline__ void ffma2(unsigned long long &d, unsigned long long a, unsigned long long b) {
    asm("fma.rn.f32x2 %0, %1, %2, %0;" : "+l"(d) : "l"(a), "l"(b));
}
__device__ __forceinline__ unsigned long long pack2(float x) {
    unsigned long long r;
    asm("mov.b64 %0, {%1, %1};" : "=l"(r) : "f"(x));
    return r;
}
__device__ __forceinline__ float2 unpack2(unsigned long long v) {
    float2 r;
    asm("mov.b64 {%0, %1}, %2;" : "=f"(r.x), "=f"(r.y) : "l"(v));
    return r;
}

// ---------------- prep: fold BN2, transpose weights, reset counters ----------------
__global__ void prep_kernel(const float* __restrict__ W2, const float* __restrict__ Winv,
                            const float* __restrict__ b2, const float* __restrict__ g2,
                            const float* __restrict__ bt2, const float* __restrict__ rm2,
                            const float* __restrict__ rv2) {
    int tid = blockIdx.x * blockDim.x + threadIdx.x;
    int nth = gridDim.x * blockDim.x;
    if (tid < 8) g_cnt[tid] = 0;
    if (tid < 32) {
        float a2 = g2[tid] * rsqrtf(rv2[tid] + 1e-5f);
        g_a2[tid] = a2;
        g_k2[tid] = (b2[tid] - rm2[tid]) * a2 + bt2[tid];
    }
    for (int i = tid; i < 27 * 32 * 32; i += nth) {
        int k = i / 1024, r = i % 1024, ci = r / 32, co = r % 32;
        g_W2T[i] = W2[(co * 32 + ci) * 27 + k];
    }
    for (int i = tid; i < 27 * 32 * 100; i += nth) {
        int k = i / 3200, r = i % 3200, ci = r / 100, co = r % 100;
        g_WT[i] = Winv[(co * 32 + ci) * 27 + k];
    }
}

// ---------------- FUSED conv1 + buildlist (both depend only on prep) --------------
__global__ __launch_bounds__(256) void conv1_aux_kernel(
        const float* __restrict__ x, const int* __restrict__ mask0,
        const float* __restrict__ W1,
        const float* __restrict__ b1, const float* __restrict__ g1,
        const float* __restrict__ bt1, const float* __restrict__ rm1,
        const float* __restrict__ rv1) {
    int b = blockIdx.x;
    int tid = threadIdx.x;

    if (b >= CONV1_BLOCKS) {
        // ---- buildlist branch ----
        __shared__ int lc[8], lb[8];
        int i = (b - CONV1_BLOCKS) * 256 + tid;
        if (tid < 8) lc[tid] = 0;
        __syncthreads();
        int cls = -1, myp = 0;
        if (i < NB * DDD && mask0[i]) {
            int r = i % DDD;
            int oz = r / DD;
            int r2 = r % DD;
            int oy = r2 / D0;
            int ox = r2 % D0;
            cls = ((oz & 1) << 2) | ((oy & 1) << 1) | (ox & 1);
            myp = atomicAdd(&lc[cls], 1);
        }
        __syncthreads();
        if (tid < 8 && lc[tid] > 0) lb[tid] = atomicAdd(&g_cnt[tid], lc[tid]);
        __syncthreads();
        if (cls >= 0) g_list[cls * LIST_STRIDE + lb[cls] + myp] = i;
        return;
    }

    // ---- conv1 branch: 256 thr = 32x * 8oy ----
    __shared__ float w1s[27 * 32];
    __shared__ float a1s[32], k1s[32];
    for (int i = tid; i < 864; i += 256) {
        int k = i >> 5, c = i & 31;
        w1s[i] = W1[c * 27 + k];
    }
    if (tid < 32) {
        float a = g1[tid] * rsqrtf(rv1[tid] + 1e-5f);
        a1s[tid] = a;
        k1s[tid] = (b1[tid] - rm1[tid]) * a + bt1[tid];
    }
    __syncthreads();

    int bx = b & 3;
    int oz = (b >> 2) & 31;
    int n  = b >> 7;
    int ox = tid & 31;
    int oy = bx * 8 + (tid >> 5);

    float acc[32];
#pragma unroll
    for (int c = 0; c < 32; c++) acc[c] = 0.f;
    int cnt = 0;
    const float* xb = x + n * DDD;
    const int*   mb = mask0 + n * DDD;

    for (int kd = 0; kd < 3; kd++)
        for (int kh = 0; kh < 3; kh++) {
            int base = (2 * oz + kd) * DD + (2 * oy + kh) * D0 + 2 * ox;
#pragma unroll
            for (int kw = 0; kw < 3; kw++) {
                float v = xb[base + kw];
                cnt += mb[base + kw];
                const float* wq = &w1s[((kd * 3 + kh) * 3 + kw) * 32];
#pragma unroll
                for (int c = 0; c < 32; c++) acc[c] += v * wq[c];
            }
        }

    float m = (cnt > 0) ? 1.f : 0.f;
    g_m1[n * SSS + (oz * S + oy) * S + ox] = m;
    float* hp = &g_h1[n * (C2 * PVOL) + (oz + 1) * PSLAB + (oy + 1) * PROW + (ox + 1)];
#pragma unroll
    for (int c = 0; c < 32; c++)
        hp[c * PVOL] = fmaxf(acc[c] * a1s[c] + k1s[c], 0.f) * m;
}

// ---------------- FUSED conv2 + zero-fill ----------------------------------------
__global__ __launch_bounds__(256) void conv2_zero_kernel(float* __restrict__ out, int out_size) {
    int b = blockIdx.x;
    int tid = threadIdx.x;

    if (b >= CONV2_BLOCKS) {
        // ---- zero branch ----
        int zb = b - CONV2_BLOCKS;
        int n4 = out_size >> 2;
        float4* o4 = (float4*)out;
        float4 z = make_float4(0.f, 0.f, 0.f, 0.f);
        int base = zb * 1024 + tid;
#pragma unroll
        for (int k = 0; k < 4; k++) {
            int idx = base + k * 256;
            if (idx < n4) o4[idx] = z;
        }
        if (zb == 0 && tid == 0)
            for (int j = n4 << 2; j < out_size; j++) out[j] = 0.f;
        return;
    }

    // ---- conv2 branch ----
    extern __shared__ float w2s[];   // [tap][ci][co 16 for this half]
    int ch = b & 1;
    {
        const float4* src = (const float4*)g_W2T;
        float4* dst = (float4*)w2s;
        for (int i = tid; i < 27 * 32 * 4; i += 256) {
            int tc = i >> 2, j = i & 3;
            dst[tc * 4 + j] = src[tc * 8 + ch * 4 + j];
        }
    }
    __syncthreads();

    int xh = tid & 15;
    int cq = (tid >> 4) & 1;
    int oy = ((b >> 1) & 3) * 8 + (tid >> 5);
    int oz = (b >> 3) & 31;
    int n  = b >> 8;
    int cob = cq * 8;
    int cobase = ch * 16 + cob;

    unsigned long long accA[4], accB[4];
#pragma unroll
    for (int i = 0; i < 4; i++) { accA[i] = 0ull; accB[i] = 0ull; }

    const float* hbase = g_h1 + n * (C2 * PVOL) + oz * PSLAB + oy * PROW + 2 * xh;

#pragma unroll
    for (int kd = 0; kd < 3; kd++) {
#pragma unroll
        for (int kh = 0; kh < 3; kh++) {
            const float* rowp = hbase + kd * PSLAB + kh * PROW;
            int tap0 = (kd * 3 + kh) * 3;
            const float* wt0 = &w2s[(tap0 + 0) * 512 + cob];
            const float* wt1 = &w2s[(tap0 + 1) * 512 + cob];
            const float* wt2 = &w2s[(tap0 + 2) * 512 + cob];
#pragma unroll 4
            for (int ci = 0; ci < 32; ci++) {
                const float2* rp2 = (const float2*)(rowp + ci * PVOL);
                float2 p01 = rp2[0];
                float2 p23 = rp2[1];
                unsigned long long hh0 = pack2(p01.x);
                unsigned long long hh1 = pack2(p01.y);
                unsigned long long hh2 = pack2(p23.x);
                unsigned long long hh3 = pack2(p23.y);
                const ulonglong2* wq0 = (const ulonglong2*)(wt0 + ci * 16);
                const ulonglong2* wq1 = (const ulonglong2*)(wt1 + ci * 16);
                const ulonglong2* wq2 = (const ulonglong2*)(wt2 + ci * 16);
#pragma unroll
                for (int q = 0; q < 2; q++) {
                    ulonglong2 w0 = wq0[q];
                    ulonglong2 w1 = wq1[q];
                    ulonglong2 w2 = wq2[q];
                    ffma2(accA[2 * q],     w0.x, hh0);
                    ffma2(accA[2 * q + 1], w0.y, hh0);
                    ffma2(accB[2 * q],     w0.x, hh1);
                    ffma2(accB[2 * q + 1], w0.y, hh1);
                    ffma2(accA[2 * q],     w1.x, hh1);
                    ffma2(accA[2 * q + 1], w1.y, hh1);
                    ffma2(accB[2 * q],     w1.x, hh2);
                    ffma2(accB[2 * q + 1], w1.y, hh2);
                    ffma2(accA[2 * q],     w2.x, hh2);
                    ffma2(accA[2 * q + 1], w2.y, hh2);
                    ffma2(accB[2 * q],     w2.x, hh3);
                    ffma2(accB[2 * q + 1], w2.y, hh3);
                }
            }
        }
    }

    int loc0 = (oz * S + oy) * S + 2 * xh;
    float m0 = g_m1[n * SSS + loc0];
    float m1v = g_m1[n * SSS + loc0 + 1];
    float* op0 = &g_h2[(n * SSS + loc0) * 32 + cobase];
    float* op1 = op0 + 32;
#pragma unroll
    for (int j = 0; j < 4; j++) {
        float2 va = unpack2(accA[j]);
        float2 vb = unpack2(accB[j]);
        int c0 = cobase + 2 * j, c1 = c0 + 1;
        float a0 = g_a2[c0], a1 = g_a2[c1], k0 = g_k2[c0], k1 = g_k2[c1];
        op0[2 * j]     = fmaxf(va.x * a0 + k0, 0.f) * m0;
        op0[2 * j + 1] = fmaxf(va.y * a1 + k1, 0.f) * m0;
        op1[2 * j]     = fmaxf(vb.x * a0 + k0, 0.f) * m1v;
        op1[2 * j + 1] = fmaxf(vb.y * a1 + k1, 0.f) * m1v;
    }
}

// ---------------- inverse conv: class-templated body (compile-time tap set) -------
template<int PZ, int PY, int PX>
__device__ __forceinline__ void inv_body(
        int cls, const float* __restrict__ binv, float* __restrict__ out,
        float (&h2s)[8 * 32 * GP], int (&sbase)[G * 8], int (&ssite)[G], int (&sout)[G]) {
    constexpr int NDZ = PZ ? 1 : 2, NDY = PY ? 1 : 2, NDX = PX ? 1 : 2;
    constexpr int NUMT = NDZ * NDY * NDX;
    constexpr int SX = (NDX == 2) ? 1 : 0;
    constexpr int SY = (NDY == 2) ? 1 : 0;
    constexpr int LT = (NUMT == 8) ? 3 : (NUMT == 4) ? 2 : (NUMT == 2) ? 1 : 0;

    int count = g_cnt[cls];
    int base = blockIdx.x * G;
    if (base >= count) return;
    int tid = threadIdx.x;
    int ng = count - base;
    if (ng > G) ng = G;

    if (tid < ng) {
        int s = g_list[cls * LIST_STRIDE + base + tid];
        ssite[tid] = s;
        sout[tid] = s + ((s >= DDD) ? 99 * DDD : 0);
    }
    __syncthreads();

    for (int i = tid; i < ng * NUMT; i += 128) {
        int g = i >> LT, t = i & (NUMT - 1);
        int s = ssite[g];
        int n = s / DDD;
        int r = s % DDD;
        int oz = r / DD;
        int r2 = r % DD;
        int oy = r2 / D0;
        int ox = r2 % D0;
        int tz = t >> (SX + SY), ty = (t >> SX) & (NDY - 1), tx = t & (NDX - 1);
        int kd = PZ ? 1 : tz * 2, kh = PY ? 1 : ty * 2, kw = PX ? 1 : tx * 2;
        int iz = (oz + kd - 2) >> 1;
        int iy = (oy + kh - 2) >> 1;
        int ix = (ox + kw - 2) >> 1;
        bool v = ((unsigned)iz < 32u) && ((unsigned)iy < 32u) && ((unsigned)ix < 32u);
        sbase[g * 8 + t] = v ? ((((n * S + iz) * S + iy) * S + ix) * 32) : -1;
    }
    __syncthreads();

    for (int i = tid; i < G * NUMT * 32; i += 128) {
        int ci = i & 31;
        int gt = i >> 5;
        int g = gt >> LT, t = gt & (NUMT - 1);
        int b = (g < ng) ? sbase[g * 8 + t] : -1;
        h2s[(t * 32 + ci) * GP + g] = (b >= 0) ? g_h2[b + ci] : 0.f;
    }
    __syncthreads();

    int co = tid;
    bool cok = (co < CO);
    float bv = cok ? __ldg(&binv[co]) : 0.f;
    unsigned long long acc2[16];
    unsigned long long bb = pack2(bv);
#pragma unroll
    for (int j = 0; j < 16; j++) acc2[j] = bb;

#pragma unroll 2
    for (int ci = 0; ci < 32; ci++) {
        float wv[NUMT];
#pragma unroll
        for (int t = 0; t < NUMT; t++) {
            int tz = t >> (SX + SY), ty = (t >> SX) & (NDY - 1), tx = t & (NDX - 1);
            int kd = PZ ? 1 : tz * 2, kh = PY ? 1 : ty * 2, kw = PX ? 1 : tx * 2;
            int tap = (kd * 3 + kh) * 3 + kw;   // compile-time after unroll
            wv[t] = cok ? __ldg(g_WT + tap * 3200 + ci * 100 + co) : 0.f;
        }
#pragma unroll
        for (int t = 0; t < NUMT; t++) {
            unsigned long long ww = pack2(wv[t]);
            const ulonglong2* hq = (const ulonglong2*)(&h2s[(t * 32 + ci) * GP]);
#pragma unroll
            for (int q = 0; q < 8; q++) {
                ulonglong2 hv = hq[q];
                ffma2(acc2[2 * q],     ww, hv.x);
                ffma2(acc2[2 * q + 1], ww, hv.y);
            }
        }
    }

    if (cok) {
        int cd = co * DDD;
#pragma unroll
        for (int j = 0; j < 16; j++) {
            float2 v = unpack2(acc2[j]);
            int g0 = 2 * j, g1 = 2 * j + 1;
            if (g0 < ng) out[sout[g0] + cd] = v.x;
            if (g1 < ng) out[sout[g1] + cd] = v.y;
        }
    }
}

// grid = (256, 8): blockIdx.y = parity class; 128 threads (co = tid)
__global__ __launch_bounds__(128) void invconv_kernel(const float* __restrict__ binv,
                                                      float* __restrict__ out) {
    __shared__ float h2s[8 * 32 * GP];
    __shared__ int   sbase[G * 8];
    __shared__ int   ssite[G];
    __shared__ int   sout[G];
    int cls = blockIdx.y;
    switch (cls) {
        case 0: inv_body<0,0,0>(0, binv, out, h2s, sbase, ssite, sout); break;
        case 1: inv_body<0,0,1>(1, binv, out, h2s, sbase, ssite, sout); break;
        case 2: inv_body<0,1,0>(2, binv, out, h2s, sbase, ssite, sout); break;
        case 3: inv_body<0,1,1>(3, binv, out, h2s, sbase, ssite, sout); break;
        case 4: inv_body<1,0,0>(4, binv, out, h2s, sbase, ssite, sout); break;
        case 5: inv_body<1,0,1>(5, binv, out, h2s, sbase, ssite, sout); break;
        case 6: inv_body<1,1,0>(6, binv, out, h2s, sbase, ssite, sout); break;
        default: inv_body<1,1,1>(7, binv, out, h2s, sbase, ssite, sout); break;
    }
}

// ---------------- launch ----------------
extern "C" void kernel_launch(void* const* d_in, const int* in_sizes, int n_in,
                              void* d_out, int out_size) {
    const float* x    = (const float*)d_in[0];
    const int*   mask0 = (const int*)d_in[1];
    const float* W1   = (const float*)d_in[2];
    const float* b1   = (const float*)d_in[3];
    const float* g1   = (const float*)d_in[4];
    const float* bt1  = (const float*)d_in[5];
    const float* rm1  = (const float*)d_in[6];
    const float* rv1  = (const float*)d_in[7];
    const float* W2   = (const float*)d_in[8];
    const float* b2   = (const float*)d_in[9];
    const float* g2   = (const float*)d_in[10];
    const float* bt2  = (const float*)d_in[11];
    const float* rm2  = (const float*)d_in[12];
    const float* rv2  = (const float*)d_in[13];
    const float* Winv = (const float*)d_in[14];
    const float* binv = (const float*)d_in[15];
    float* out = (float*)d_out;

    cudaFuncSetAttribute(conv2_zero_kernel, cudaFuncAttributeMaxDynamicSharedMemorySize,
                         27 * 32 * 16 * (int)sizeof(float));

    prep_kernel<<<512, 256>>>(W2, Winv, b2, g2, bt2, rm2, rv2);
    conv1_aux_kernel<<<CONV1_BLOCKS + BL_BLOCKS, 256>>>(x, mask0, W1, b1, g1, bt1, rm1, rv1);

    int n4 = out_size >> 2;
    int zblocks = (n4 + 1023) / 1024;
    conv2_zero_kernel<<<CONV2_BLOCKS + zblocks, 256, 27 * 32 * 16 * sizeof(float)>>>(out, out_size);

    invconv_kernel<<<dim3(LIST_STRIDE / G, 8), 128>>>(binv, out);
}